// round 8
// baseline (speedup 1.0000x reference)
#include <cuda_runtime.h>
#include <cstdint>

// Problem constants
#define BSZ     4
#define SEQ     2048
#define DIMSZ   512
#define HEADS   8
#define HD      64
#define M_TOT   (BSZ * SEQ)   // 8192
#define NEGV    (-1000000.0f)

// Scratch (device globals: allocation rules forbid cudaMalloc)
__device__ float g_Q[M_TOT * DIMSZ];
__device__ float g_K[M_TOT * DIMSZ];
__device__ float g_V[M_TOT * DIMSZ];
__device__ float g_A[M_TOT * DIMSZ];

// ===========================================================================
// Helpers: compute_103-safe PTX only (mma.sync / ldmatrix / cvt.rna.tf32)
// ===========================================================================
__device__ __forceinline__ uint32_t smem_u32(const void* p) {
    uint32_t a;
    asm("{ .reg .u64 t; cvta.to.shared.u64 t, %1; cvt.u32.u64 %0, t; }"
        : "=r"(a) : "l"(p));
    return a;
}

__device__ __forceinline__ uint32_t f2tf(float f) {
    uint32_t u;
    asm("cvt.rna.tf32.f32 %0, %1;" : "=r"(u) : "f"(f));
    return u;
}

__device__ __forceinline__ uint4 cvt4(float4 v) {
    uint4 t;
    t.x = f2tf(v.x); t.y = f2tf(v.y); t.z = f2tf(v.z); t.w = f2tf(v.w);
    return t;
}

__device__ __forceinline__ void ldsm4(uint32_t& r0, uint32_t& r1,
                                      uint32_t& r2, uint32_t& r3,
                                      uint32_t addr) {
    asm volatile("ldmatrix.sync.aligned.m8n8.x4.shared.b16 {%0,%1,%2,%3}, [%4];"
                 : "=r"(r0), "=r"(r1), "=r"(r2), "=r"(r3) : "r"(addr));
}

// D (fp32) += A(tf32 row-major m16 x k8) * B(tf32 col-major k8 x n8)
__device__ __forceinline__ void mma_tf32(float* d, const uint32_t* a,
                                         uint32_t b0, uint32_t b1) {
    asm volatile(
        "mma.sync.aligned.m16n8k8.row.col.f32.tf32.tf32.f32 "
        "{%0,%1,%2,%3}, {%4,%5,%6,%7}, {%8,%9}, {%0,%1,%2,%3};"
        : "+f"(d[0]), "+f"(d[1]), "+f"(d[2]), "+f"(d[3])
        : "r"(a[0]), "r"(a[1]), "r"(a[2]), "r"(a[3]), "r"(b0), "r"(b1));
}

// ===========================================================================
// GEMM:  D[M,512] = A[M,512] * W[512,512]^T   (tf32 mma, fp32 acc)
// CTA tile 128(m) x 64(n), 256 threads, warp tile 32x32, K-chunks of 32.
// SMEM rows = 32 floats (128B, 8 x 16B chunks), xor-swizzled, double-buffered.
// ===========================================================================
#define G_STAGE 24576      // A tile 16KB + W tile 8KB
#define G_SMEM  (2 * G_STAGE)

__global__ __launch_bounds__(256, 2)
void gemm_tc(const float* __restrict__ A, const float* __restrict__ W,
             float* __restrict__ D)
{
    extern __shared__ char sm[];
    const uint32_t sb = smem_u32(sm);
    const int tid = threadIdx.x;
    const int l   = tid & 31;
    const int wid = tid >> 5;
    const int wm  = wid & 3;        // 4 warps along M
    const int wn  = wid >> 2;       // 2 warps along N
    const int rowBase = blockIdx.y * 128;
    const int colBase = blockIdx.x * 64;

    float4 pa[4], pw[2];

    // prefetch chunk c into regs
    auto prefetch = [&](int c) {
#pragma unroll
        for (int i = 0; i < 4; i++) {
            int idx = tid + i * 256;           // 0..1023
            int r = idx >> 3, cc = idx & 7;
            pa[i] = *(const float4*)&A[(size_t)(rowBase + r) * DIMSZ + c * 32 + cc * 4];
        }
#pragma unroll
        for (int i = 0; i < 2; i++) {
            int idx = tid + i * 256;           // 0..511
            int r = idx >> 3, cc = idx & 7;
            pw[i] = *(const float4*)&W[(size_t)(colBase + r) * DIMSZ + c * 32 + cc * 4];
        }
    };
    // store regs into buffer (tf32-converted, swizzled)
    auto stage = [&](int buf) {
        char* base = sm + buf * G_STAGE;
#pragma unroll
        for (int i = 0; i < 4; i++) {
            int idx = tid + i * 256;
            int r = idx >> 3, cc = idx & 7;
            *(uint4*)(base + r * 128 + ((cc ^ (r & 7)) << 4)) = cvt4(pa[i]);
        }
#pragma unroll
        for (int i = 0; i < 2; i++) {
            int idx = tid + i * 256;
            int r = idx >> 3, cc = idx & 7;
            *(uint4*)(base + 16384 + r * 128 + ((cc ^ (r & 7)) << 4)) = cvt4(pw[i]);
        }
    };

    float acc[2][4][4];
#pragma unroll
    for (int im = 0; im < 2; im++)
#pragma unroll
        for (int j = 0; j < 4; j++)
#pragma unroll
            for (int q = 0; q < 4; q++) acc[im][j][q] = 0.f;

    prefetch(0);
    stage(0);

    for (int c = 0; c < 16; ++c) {
        __syncthreads();
        if (c < 15) prefetch(c + 1);
        const uint32_t abase = sb + (c & 1) * G_STAGE;
        const uint32_t wbase = abase + 16384;
#pragma unroll
        for (int s = 0; s < 4; ++s) {
            uint32_t a[2][4];
#pragma unroll
            for (int im = 0; im < 2; im++) {
                int r = 32 * wm + 16 * im + (l & 7) + (((l >> 3) & 1) << 3);
                int cc = (2 * s + (l >> 4)) ^ (r & 7);
                ldsm4(a[im][0], a[im][1], a[im][2], a[im][3],
                      abase + r * 128 + (cc << 4));
            }
            uint32_t b[4][2];
#pragma unroll
            for (int p = 0; p < 2; p++) {
                int r = 32 * wn + 16 * p + (l & 7) + ((l >> 4) << 3);
                int cc = (2 * s + ((l >> 3) & 1)) ^ (r & 7);
                ldsm4(b[2 * p][0], b[2 * p][1], b[2 * p + 1][0], b[2 * p + 1][1],
                      wbase + r * 128 + (cc << 4));
            }
#pragma unroll
            for (int im = 0; im < 2; im++)
#pragma unroll
                for (int j = 0; j < 4; j++)
                    mma_tf32(acc[im][j], a[im], b[j][0], b[j][1]);
        }
        if (c < 15) stage((c + 1) & 1);
    }

    // epilogue
#pragma unroll
    for (int im = 0; im < 2; im++) {
        int r0 = rowBase + 32 * wm + 16 * im + (l >> 2);
#pragma unroll
        for (int j = 0; j < 4; j++) {
            int col = colBase + 32 * wn + 8 * j + 2 * (l & 3);
            *(float2*)&D[(size_t)r0 * DIMSZ + col] =
                make_float2(acc[im][j][0], acc[im][j][1]);
            *(float2*)&D[(size_t)(r0 + 8) * DIMSZ + col] =
                make_float2(acc[im][j][2], acc[im][j][3]);
        }
    }
}

// ===========================================================================
// Fused flash-attention with tf32 mma.sync.
// CTA: 128 q-rows of one (b,h); 8 warps; warp owns 16 q-rows.
// KV tiles of 64.  SMEM rows = 64 floats (256B, 16 chunks), xor-swizzled.
//   Qs[128][64]  (q, d)    pre-scaled by 1/8, tf32
//   Ks[64][64]   (key, d)  tf32
//   Vt[64][64]   (d, key)  tf32 (transposed during staging)
//   Ps[128][64]  (q, key)  tf32
// ===========================================================================
#define AT_QS   0
#define AT_KS   32768
#define AT_VT   49152
#define AT_PS   65536
#define AT_MSK  98304
#define AT_SMEM (98304 + 256)

__global__ __launch_bounds__(256, 2)
void attn_tc(const float* __restrict__ Q, const float* __restrict__ K,
             const float* __restrict__ V, const int* __restrict__ mask,
             float* __restrict__ Aout)
{
    extern __shared__ char sm[];
    const uint32_t sb = smem_u32(sm);
    int* msk = (int*)(sm + AT_MSK);

    const int tid = threadIdx.x;
    const int l   = tid & 31;
    const int w   = tid >> 5;       // warp id: rows 16*w
    const int b   = blockIdx.z;
    const int h   = blockIdx.y;
    const int qb  = blockIdx.x * 128;

    const float* Qb = Q + ((size_t)b * SEQ) * DIMSZ + h * HD;
    const float* Kb = K + ((size_t)b * SEQ) * DIMSZ + h * HD;
    const float* Vb = V + ((size_t)b * SEQ) * DIMSZ + h * HD;
    const int*   mb = mask + b * SEQ;

    // Load Q tile once: (q,d), scaled 1/8, tf32, swizzled
#pragma unroll
    for (int i = 0; i < 8; i++) {
        int idx = tid + i * 256;      // 0..2047
        int r = idx >> 4, cc = idx & 15;
        float4 v = *(const float4*)&Qb[(size_t)(qb + r) * DIMSZ + cc * 4];
        v.x *= 0.125f; v.y *= 0.125f; v.z *= 0.125f; v.w *= 0.125f;
        *(uint4*)(sm + AT_QS + r * 256 + ((cc ^ (r & 7)) << 4)) = cvt4(v);
    }

    float O[8][4];
    float m0 = -1e30f, m1 = -1e30f, l0 = 0.f, l1 = 0.f;
#pragma unroll
    for (int j = 0; j < 8; j++)
#pragma unroll
        for (int q = 0; q < 4; q++) O[j][q] = 0.f;

    for (int k0 = 0; k0 < SEQ; k0 += 64) {
        __syncthreads();   // prev tile's PV reads of Ks/Vt complete
        // stage K (natural) and V (transposed)
#pragma unroll
        for (int i = 0; i < 4; i++) {
            int idx = tid + i * 256;   // 0..1023
            int key = idx >> 4, cc = idx & 15;
            float4 kv = *(const float4*)&Kb[(size_t)(k0 + key) * DIMSZ + cc * 4];
            *(uint4*)(sm + AT_KS + key * 256 + ((cc ^ (key & 7)) << 4)) = cvt4(kv);
            float4 vv = *(const float4*)&Vb[(size_t)(k0 + key) * DIMSZ + cc * 4];
            int d0 = cc * 4;
            int kc = key >> 2, ko = (key & 3) * 4;
            *(uint32_t*)(sm + AT_VT + (d0+0) * 256 + ((kc ^ ((d0+0) & 7)) << 4) + ko) = f2tf(vv.x);
            *(uint32_t*)(sm + AT_VT + (d0+1) * 256 + ((kc ^ ((d0+1) & 7)) << 4) + ko) = f2tf(vv.y);
            *(uint32_t*)(sm + AT_VT + (d0+2) * 256 + ((kc ^ ((d0+2) & 7)) << 4) + ko) = f2tf(vv.z);
            *(uint32_t*)(sm + AT_VT + (d0+3) * 256 + ((kc ^ ((d0+3) & 7)) << 4) + ko) = f2tf(vv.w);
        }
        if (tid < 64) msk[tid] = mb[k0 + tid];
        __syncthreads();

        // ---- S = Qs * Ks^T : warp rows 16w, 8 key-atoms, 8 d-steps ----
        float S[8][4];
#pragma unroll
        for (int j = 0; j < 8; j++)
#pragma unroll
            for (int q = 0; q < 4; q++) S[j][q] = 0.f;

#pragma unroll
        for (int s = 0; s < 8; ++s) {
            uint32_t a[4];
            {
                int r = 16 * w + (l & 7) + (((l >> 3) & 1) << 3);
                int cc = (2 * s + (l >> 4)) ^ (r & 7);
                ldsm4(a[0], a[1], a[2], a[3], sb + AT_QS + r * 256 + (cc << 4));
            }
            uint32_t bq[8][2];
#pragma unroll
            for (int p = 0; p < 4; p++) {
                int r = 16 * p + (l & 7) + ((l >> 4) << 3);
                int cc = (2 * s + ((l >> 3) & 1)) ^ (r & 7);
                ldsm4(bq[2*p][0], bq[2*p][1], bq[2*p+1][0], bq[2*p+1][1],
                      sb + AT_KS + r * 256 + (cc << 4));
            }
#pragma unroll
            for (int j = 0; j < 8; j++)
                mma_tf32(S[j], a, bq[j][0], bq[j][1]);
        }

        // ---- mask (Q pre-scaled, so S already /8) ----
#pragma unroll
        for (int j = 0; j < 8; j++) {
            int kA = 8 * j + 2 * (l & 3);
            int mA = msk[kA], mB = msk[kA + 1];
            S[j][0] = mA ? S[j][0] : NEGV;
            S[j][1] = mB ? S[j][1] : NEGV;
            S[j][2] = mA ? S[j][2] : NEGV;
            S[j][3] = mB ? S[j][3] : NEGV;
        }

        // ---- online softmax (rows l/4 and l/4+8; quad = lanes sharing l/4) ----
        float mx0 = -1e30f, mx1 = -1e30f;
#pragma unroll
        for (int j = 0; j < 8; j++) {
            mx0 = fmaxf(mx0, fmaxf(S[j][0], S[j][1]));
            mx1 = fmaxf(mx1, fmaxf(S[j][2], S[j][3]));
        }
        mx0 = fmaxf(mx0, __shfl_xor_sync(0xffffffffu, mx0, 1));
        mx0 = fmaxf(mx0, __shfl_xor_sync(0xffffffffu, mx0, 2));
        mx1 = fmaxf(mx1, __shfl_xor_sync(0xffffffffu, mx1, 1));
        mx1 = fmaxf(mx1, __shfl_xor_sync(0xffffffffu, mx1, 2));

        float mn0 = fmaxf(m0, mx0), mn1 = fmaxf(m1, mx1);
        float cr0 = __expf(m0 - mn0), cr1 = __expf(m1 - mn1);
        m0 = mn0; m1 = mn1;

        float rs0 = 0.f, rs1 = 0.f;
        const int qr  = 16 * w + (l >> 2);
        const int kAc = 2 * (l & 3);          // key offset within atom
#pragma unroll
        for (int j = 0; j < 8; j++) {
            float p0 = __expf(S[j][0] - mn0);
            float p1 = __expf(S[j][1] - mn0);
            float p2 = __expf(S[j][2] - mn1);
            float p3 = __expf(S[j][3] - mn1);
            rs0 += p0 + p1; rs1 += p2 + p3;
            // store P (tf32) to Ps[q][key]
            int kA = 8 * j + kAc;
            int kc = kA >> 2, ko = (kA & 3) * 4;
            *(uint2*)(sm + AT_PS + qr * 256 + ((kc ^ (qr & 7)) << 4) + ko) =
                make_uint2(f2tf(p0), f2tf(p1));
            int qr8 = qr + 8;
            *(uint2*)(sm + AT_PS + qr8 * 256 + ((kc ^ (qr8 & 7)) << 4) + ko) =
                make_uint2(f2tf(p2), f2tf(p3));
        }
        rs0 += __shfl_xor_sync(0xffffffffu, rs0, 1);
        rs0 += __shfl_xor_sync(0xffffffffu, rs0, 2);
        rs1 += __shfl_xor_sync(0xffffffffu, rs1, 1);
        rs1 += __shfl_xor_sync(0xffffffffu, rs1, 2);
        l0 = l0 * cr0 + rs0;
        l1 = l1 * cr1 + rs1;

#pragma unroll
        for (int j = 0; j < 8; j++) {
            O[j][0] *= cr0; O[j][1] *= cr0;
            O[j][2] *= cr1; O[j][3] *= cr1;
        }
        __syncwarp();   // Ps rows are warp-private; order stores before ldmatrix

        // ---- O += P * V : 8 d-atoms, 8 key-steps ----
#pragma unroll
        for (int s = 0; s < 8; ++s) {
            uint32_t a[4];
            {
                int r = 16 * w + (l & 7) + (((l >> 3) & 1) << 3);
                int cc = (2 * s + (l >> 4)) ^ (r & 7);
                ldsm4(a[0], a[1], a[2], a[3], sb + AT_PS + r * 256 + (cc << 4));
            }
            uint32_t bv[8][2];
#pragma unroll
            for (int p = 0; p < 4; p++) {
                int r = 16 * p + (l & 7) + ((l >> 4) << 3);   // r = d row
                int cc = (2 * s + ((l >> 3) & 1)) ^ (r & 7);
                ldsm4(bv[2*p][0], bv[2*p][1], bv[2*p+1][0], bv[2*p+1][1],
                      sb + AT_VT + r * 256 + (cc << 4));
            }
#pragma unroll
            for (int j = 0; j < 8; j++)
                mma_tf32(O[j], a, bv[j][0], bv[j][1]);
        }
    }

    // ---- epilogue: normalize, write head-merged fp32 ----
    const float inv0 = 1.0f / l0, inv1 = 1.0f / l1;
    const int qr = qb + 16 * w + (l >> 2);
#pragma unroll
    for (int j = 0; j < 8; j++) {
        int col = h * HD + 8 * j + 2 * (l & 3);
        *(float2*)&Aout[((size_t)b * SEQ + qr) * DIMSZ + col] =
            make_float2(O[j][0] * inv0, O[j][1] * inv0);
        *(float2*)&Aout[((size_t)b * SEQ + qr + 8) * DIMSZ + col] =
            make_float2(O[j][2] * inv1, O[j][3] * inv1);
    }
}

// ---------------------------------------------------------------------------
extern "C" void kernel_launch(void* const* d_in, const int* in_sizes, int n_in,
                              void* d_out, int out_size)
{
    (void)in_sizes; (void)n_in; (void)out_size;
    const float* x    = (const float*)d_in[0];
    const float* Wq   = (const float*)d_in[1];
    const float* Wk   = (const float*)d_in[2];
    const float* Wv   = (const float*)d_in[3];
    const float* Wo   = (const float*)d_in[4];
    const int*   mask = (const int*)d_in[5];
    float*       out  = (float*)d_out;

    float *Qp = nullptr, *Kp = nullptr, *Vp = nullptr, *Ap = nullptr;
    cudaGetSymbolAddress((void**)&Qp, g_Q);
    cudaGetSymbolAddress((void**)&Kp, g_K);
    cudaGetSymbolAddress((void**)&Vp, g_V);
    cudaGetSymbolAddress((void**)&Ap, g_A);

    cudaFuncSetAttribute(gemm_tc,
                         cudaFuncAttributeMaxDynamicSharedMemorySize, G_SMEM);
    cudaFuncSetAttribute(attn_tc,
                         cudaFuncAttributeMaxDynamicSharedMemorySize, AT_SMEM);

    dim3 ggrid(DIMSZ / 64, M_TOT / 128);   // (8, 64)
    gemm_tc<<<ggrid, 256, G_SMEM>>>(x, Wq, Qp);
    gemm_tc<<<ggrid, 256, G_SMEM>>>(x, Wk, Kp);
    gemm_tc<<<ggrid, 256, G_SMEM>>>(x, Wv, Vp);

    attn_tc<<<dim3(SEQ / 128, HEADS, BSZ), 256, AT_SMEM>>>(Qp, Kp, Vp, mask, Ap);

    gemm_tc<<<ggrid, 256, G_SMEM>>>(Ap, Wo, out);
}

// round 9
// speedup vs baseline: 1.0013x; 1.0013x over previous
#include <cuda_runtime.h>
#include <cstdint>

// Problem constants
#define BSZ     4
#define SEQ     2048
#define DIMSZ   512
#define HEADS   8
#define HD      64
#define M_TOT   (BSZ * SEQ)   // 8192
#define NEGV    (-1000000.0f)

// Scratch (device globals: allocation rules forbid cudaMalloc)
__device__ float g_Q[M_TOT * DIMSZ];
__device__ float g_K[M_TOT * DIMSZ];
__device__ float g_V[M_TOT * DIMSZ];
__device__ float g_A[M_TOT * DIMSZ];

// ===========================================================================
// Helpers: compute_103-safe PTX only (mma.sync / ldmatrix / cvt.rna.tf32)
// ===========================================================================
__device__ __forceinline__ uint32_t smem_u32(const void* p) {
    uint32_t a;
    asm("{ .reg .u64 t; cvta.to.shared.u64 t, %1; cvt.u32.u64 %0, t; }"
        : "=r"(a) : "l"(p));
    return a;
}

__device__ __forceinline__ uint32_t f2tf(float f) {
    uint32_t u;
    asm("cvt.rna.tf32.f32 %0, %1;" : "=r"(u) : "f"(f));
    return u;
}

__device__ __forceinline__ uint4 cvt4(float4 v) {
    uint4 t;
    t.x = f2tf(v.x); t.y = f2tf(v.y); t.z = f2tf(v.z); t.w = f2tf(v.w);
    return t;
}

__device__ __forceinline__ void ldsm4(uint32_t& r0, uint32_t& r1,
                                      uint32_t& r2, uint32_t& r3,
                                      uint32_t addr) {
    asm volatile("ldmatrix.sync.aligned.m8n8.x4.shared.b16 {%0,%1,%2,%3}, [%4];"
                 : "=r"(r0), "=r"(r1), "=r"(r2), "=r"(r3) : "r"(addr));
}

// D (fp32) += A(tf32 row-major m16 x k8) * B(tf32 col-major k8 x n8)
__device__ __forceinline__ void mma_tf32(float* d, const uint32_t* a,
                                         uint32_t b0, uint32_t b1) {
    asm volatile(
        "mma.sync.aligned.m16n8k8.row.col.f32.tf32.tf32.f32 "
        "{%0,%1,%2,%3}, {%4,%5,%6,%7}, {%8,%9}, {%0,%1,%2,%3};"
        : "+f"(d[0]), "+f"(d[1]), "+f"(d[2]), "+f"(d[3])
        : "r"(a[0]), "r"(a[1]), "r"(a[2]), "r"(a[3]), "r"(b0), "r"(b1));
}

// ===========================================================================
// GEMM:  D[M,512] = A[M,512] * W[512,512]^T   (tf32 mma, fp32 acc)
// CTA tile 128(m) x 64(n), 256 threads, warp tile 32x32, K-chunks of 32.
// SMEM rows = 32 floats (128B, 8 x 16B chunks), xor-swizzled, double-buffered.
// ===========================================================================
#define G_STAGE 24576      // A tile 16KB + W tile 8KB
#define G_SMEM  (2 * G_STAGE)

__global__ __launch_bounds__(256, 2)
void gemm_tc(const float* __restrict__ A, const float* __restrict__ W,
             float* __restrict__ D)
{
    extern __shared__ char sm[];
    const uint32_t sb = smem_u32(sm);
    const int tid = threadIdx.x;
    const int l   = tid & 31;
    const int wid = tid >> 5;
    const int wm  = wid & 3;        // 4 warps along M
    const int wn  = wid >> 2;       // 2 warps along N
    const int rowBase = blockIdx.y * 128;
    const int colBase = blockIdx.x * 64;

    float4 pa[4], pw[2];

    // prefetch chunk c into regs
    auto prefetch = [&](int c) {
#pragma unroll
        for (int i = 0; i < 4; i++) {
            int idx = tid + i * 256;           // 0..1023
            int r = idx >> 3, cc = idx & 7;
            pa[i] = *(const float4*)&A[(size_t)(rowBase + r) * DIMSZ + c * 32 + cc * 4];
        }
#pragma unroll
        for (int i = 0; i < 2; i++) {
            int idx = tid + i * 256;           // 0..511
            int r = idx >> 3, cc = idx & 7;
            pw[i] = *(const float4*)&W[(size_t)(colBase + r) * DIMSZ + c * 32 + cc * 4];
        }
    };
    // store regs into buffer (tf32-converted, swizzled)
    auto stage = [&](int buf) {
        char* base = sm + buf * G_STAGE;
#pragma unroll
        for (int i = 0; i < 4; i++) {
            int idx = tid + i * 256;
            int r = idx >> 3, cc = idx & 7;
            *(uint4*)(base + r * 128 + ((cc ^ (r & 7)) << 4)) = cvt4(pa[i]);
        }
#pragma unroll
        for (int i = 0; i < 2; i++) {
            int idx = tid + i * 256;
            int r = idx >> 3, cc = idx & 7;
            *(uint4*)(base + 16384 + r * 128 + ((cc ^ (r & 7)) << 4)) = cvt4(pw[i]);
        }
    };

    float acc[2][4][4];
#pragma unroll
    for (int im = 0; im < 2; im++)
#pragma unroll
        for (int j = 0; j < 4; j++)
#pragma unroll
            for (int q = 0; q < 4; q++) acc[im][j][q] = 0.f;

    prefetch(0);
    stage(0);

    for (int c = 0; c < 16; ++c) {
        __syncthreads();
        if (c < 15) prefetch(c + 1);
        const uint32_t abase = sb + (c & 1) * G_STAGE;
        const uint32_t wbase = abase + 16384;
#pragma unroll
        for (int s = 0; s < 4; ++s) {
            uint32_t a[2][4];
#pragma unroll
            for (int im = 0; im < 2; im++) {
                int r = 32 * wm + 16 * im + (l & 7) + (((l >> 3) & 1) << 3);
                int cc = (2 * s + (l >> 4)) ^ (r & 7);
                ldsm4(a[im][0], a[im][1], a[im][2], a[im][3],
                      abase + r * 128 + (cc << 4));
            }
            uint32_t b[4][2];
#pragma unroll
            for (int p = 0; p < 2; p++) {
                int r = 32 * wn + 16 * p + (l & 7) + ((l >> 4) << 3);
                int cc = (2 * s + ((l >> 3) & 1)) ^ (r & 7);
                ldsm4(b[2 * p][0], b[2 * p][1], b[2 * p + 1][0], b[2 * p + 1][1],
                      wbase + r * 128 + (cc << 4));
            }
#pragma unroll
            for (int im = 0; im < 2; im++)
#pragma unroll
                for (int j = 0; j < 4; j++)
                    mma_tf32(acc[im][j], a[im], b[j][0], b[j][1]);
        }
        if (c < 15) stage((c + 1) & 1);
    }

    // epilogue
#pragma unroll
    for (int im = 0; im < 2; im++) {
        int r0 = rowBase + 32 * wm + 16 * im + (l >> 2);
#pragma unroll
        for (int j = 0; j < 4; j++) {
            int col = colBase + 32 * wn + 8 * j + 2 * (l & 3);
            *(float2*)&D[(size_t)r0 * DIMSZ + col] =
                make_float2(acc[im][j][0], acc[im][j][1]);
            *(float2*)&D[(size_t)(r0 + 8) * DIMSZ + col] =
                make_float2(acc[im][j][2], acc[im][j][3]);
        }
    }
}

// ===========================================================================
// Fused flash-attention with tf32 mma.sync.
// CTA: 128 q-rows of one (b,h); 8 warps; warp owns 16 q-rows.
// KV tiles of 64.  SMEM rows = 64 floats (256B, 16 chunks), xor-swizzled.
//   Qs[128][64]  (q, d)    pre-scaled by 1/8, tf32
//   Ks[64][64]   (key, d)  tf32
//   Vt[64][64]   (d, key)  tf32 (transposed during staging)
//   Ps[128][64]  (q, key)  tf32
// ===========================================================================
#define AT_QS   0
#define AT_KS   32768
#define AT_VT   49152
#define AT_PS   65536
#define AT_MSK  98304
#define AT_SMEM (98304 + 256)

__global__ __launch_bounds__(256, 2)
void attn_tc(const float* __restrict__ Q, const float* __restrict__ K,
             const float* __restrict__ V, const int* __restrict__ mask,
             float* __restrict__ Aout)
{
    extern __shared__ char sm[];
    const uint32_t sb = smem_u32(sm);
    int* msk = (int*)(sm + AT_MSK);

    const int tid = threadIdx.x;
    const int l   = tid & 31;
    const int w   = tid >> 5;       // warp id: rows 16*w
    const int b   = blockIdx.z;
    const int h   = blockIdx.y;
    const int qb  = blockIdx.x * 128;

    const float* Qb = Q + ((size_t)b * SEQ) * DIMSZ + h * HD;
    const float* Kb = K + ((size_t)b * SEQ) * DIMSZ + h * HD;
    const float* Vb = V + ((size_t)b * SEQ) * DIMSZ + h * HD;
    const int*   mb = mask + b * SEQ;

    // Load Q tile once: (q,d), scaled 1/8, tf32, swizzled
#pragma unroll
    for (int i = 0; i < 8; i++) {
        int idx = tid + i * 256;      // 0..2047
        int r = idx >> 4, cc = idx & 15;
        float4 v = *(const float4*)&Qb[(size_t)(qb + r) * DIMSZ + cc * 4];
        v.x *= 0.125f; v.y *= 0.125f; v.z *= 0.125f; v.w *= 0.125f;
        *(uint4*)(sm + AT_QS + r * 256 + ((cc ^ (r & 7)) << 4)) = cvt4(v);
    }

    float O[8][4];
    float m0 = -1e30f, m1 = -1e30f, l0 = 0.f, l1 = 0.f;
#pragma unroll
    for (int j = 0; j < 8; j++)
#pragma unroll
        for (int q = 0; q < 4; q++) O[j][q] = 0.f;

    for (int k0 = 0; k0 < SEQ; k0 += 64) {
        __syncthreads();   // prev tile's PV reads of Ks/Vt complete
        // stage K (natural) and V (transposed)
#pragma unroll
        for (int i = 0; i < 4; i++) {
            int idx = tid + i * 256;   // 0..1023
            int key = idx >> 4, cc = idx & 15;
            float4 kv = *(const float4*)&Kb[(size_t)(k0 + key) * DIMSZ + cc * 4];
            *(uint4*)(sm + AT_KS + key * 256 + ((cc ^ (key & 7)) << 4)) = cvt4(kv);
            float4 vv = *(const float4*)&Vb[(size_t)(k0 + key) * DIMSZ + cc * 4];
            int d0 = cc * 4;
            int kc = key >> 2, ko = (key & 3) * 4;
            *(uint32_t*)(sm + AT_VT + (d0+0) * 256 + ((kc ^ ((d0+0) & 7)) << 4) + ko) = f2tf(vv.x);
            *(uint32_t*)(sm + AT_VT + (d0+1) * 256 + ((kc ^ ((d0+1) & 7)) << 4) + ko) = f2tf(vv.y);
            *(uint32_t*)(sm + AT_VT + (d0+2) * 256 + ((kc ^ ((d0+2) & 7)) << 4) + ko) = f2tf(vv.z);
            *(uint32_t*)(sm + AT_VT + (d0+3) * 256 + ((kc ^ ((d0+3) & 7)) << 4) + ko) = f2tf(vv.w);
        }
        if (tid < 64) msk[tid] = mb[k0 + tid];
        __syncthreads();

        // ---- S = Qs * Ks^T : warp rows 16w, 8 key-atoms, 8 d-steps ----
        float S[8][4];
#pragma unroll
        for (int j = 0; j < 8; j++)
#pragma unroll
            for (int q = 0; q < 4; q++) S[j][q] = 0.f;

#pragma unroll
        for (int s = 0; s < 8; ++s) {
            uint32_t a[4];
            {
                int r = 16 * w + (l & 7) + (((l >> 3) & 1) << 3);
                int cc = (2 * s + (l >> 4)) ^ (r & 7);
                ldsm4(a[0], a[1], a[2], a[3], sb + AT_QS + r * 256 + (cc << 4));
            }
            uint32_t bq[8][2];
#pragma unroll
            for (int p = 0; p < 4; p++) {
                int r = 16 * p + (l & 7) + ((l >> 4) << 3);
                int cc = (2 * s + ((l >> 3) & 1)) ^ (r & 7);
                ldsm4(bq[2*p][0], bq[2*p][1], bq[2*p+1][0], bq[2*p+1][1],
                      sb + AT_KS + r * 256 + (cc << 4));
            }
#pragma unroll
            for (int j = 0; j < 8; j++)
                mma_tf32(S[j], a, bq[j][0], bq[j][1]);
        }

        // ---- mask (Q pre-scaled, so S already /8) ----
#pragma unroll
        for (int j = 0; j < 8; j++) {
            int kA = 8 * j + 2 * (l & 3);
            int mA = msk[kA], mB = msk[kA + 1];
            S[j][0] = mA ? S[j][0] : NEGV;
            S[j][1] = mB ? S[j][1] : NEGV;
            S[j][2] = mA ? S[j][2] : NEGV;
            S[j][3] = mB ? S[j][3] : NEGV;
        }

        // ---- online softmax (rows l/4 and l/4+8; quad = lanes sharing l/4) ----
        float mx0 = -1e30f, mx1 = -1e30f;
#pragma unroll
        for (int j = 0; j < 8; j++) {
            mx0 = fmaxf(mx0, fmaxf(S[j][0], S[j][1]));
            mx1 = fmaxf(mx1, fmaxf(S[j][2], S[j][3]));
        }
        mx0 = fmaxf(mx0, __shfl_xor_sync(0xffffffffu, mx0, 1));
        mx0 = fmaxf(mx0, __shfl_xor_sync(0xffffffffu, mx0, 2));
        mx1 = fmaxf(mx1, __shfl_xor_sync(0xffffffffu, mx1, 1));
        mx1 = fmaxf(mx1, __shfl_xor_sync(0xffffffffu, mx1, 2));

        float mn0 = fmaxf(m0, mx0), mn1 = fmaxf(m1, mx1);
        float cr0 = __expf(m0 - mn0), cr1 = __expf(m1 - mn1);
        m0 = mn0; m1 = mn1;

        float rs0 = 0.f, rs1 = 0.f;
        const int qr  = 16 * w + (l >> 2);
        const int kAc = 2 * (l & 3);          // key offset within atom
#pragma unroll
        for (int j = 0; j < 8; j++) {
            float p0 = __expf(S[j][0] - mn0);
            float p1 = __expf(S[j][1] - mn0);
            float p2 = __expf(S[j][2] - mn1);
            float p3 = __expf(S[j][3] - mn1);
            rs0 += p0 + p1; rs1 += p2 + p3;
            // store P (tf32) to Ps[q][key]
            int kA = 8 * j + kAc;
            int kc = kA >> 2, ko = (kA & 3) * 4;
            *(uint2*)(sm + AT_PS + qr * 256 + ((kc ^ (qr & 7)) << 4) + ko) =
                make_uint2(f2tf(p0), f2tf(p1));
            int qr8 = qr + 8;
            *(uint2*)(sm + AT_PS + qr8 * 256 + ((kc ^ (qr8 & 7)) << 4) + ko) =
                make_uint2(f2tf(p2), f2tf(p3));
        }
        rs0 += __shfl_xor_sync(0xffffffffu, rs0, 1);
        rs0 += __shfl_xor_sync(0xffffffffu, rs0, 2);
        rs1 += __shfl_xor_sync(0xffffffffu, rs1, 1);
        rs1 += __shfl_xor_sync(0xffffffffu, rs1, 2);
        l0 = l0 * cr0 + rs0;
        l1 = l1 * cr1 + rs1;

#pragma unroll
        for (int j = 0; j < 8; j++) {
            O[j][0] *= cr0; O[j][1] *= cr0;
            O[j][2] *= cr1; O[j][3] *= cr1;
        }
        __syncwarp();   // Ps rows are warp-private; order stores before ldmatrix

        // ---- O += P * V : 8 d-atoms, 8 key-steps ----
#pragma unroll
        for (int s = 0; s < 8; ++s) {
            uint32_t a[4];
            {
                int r = 16 * w + (l & 7) + (((l >> 3) & 1) << 3);
                int cc = (2 * s + (l >> 4)) ^ (r & 7);
                ldsm4(a[0], a[1], a[2], a[3], sb + AT_PS + r * 256 + (cc << 4));
            }
            uint32_t bv[8][2];
#pragma unroll
            for (int p = 0; p < 4; p++) {
                int r = 16 * p + (l & 7) + ((l >> 4) << 3);   // r = d row
                int cc = (2 * s + ((l >> 3) & 1)) ^ (r & 7);
                ldsm4(bv[2*p][0], bv[2*p][1], bv[2*p+1][0], bv[2*p+1][1],
                      sb + AT_VT + r * 256 + (cc << 4));
            }
#pragma unroll
            for (int j = 0; j < 8; j++)
                mma_tf32(O[j], a, bv[j][0], bv[j][1]);
        }
    }

    // ---- epilogue: normalize, write head-merged fp32 ----
    const float inv0 = 1.0f / l0, inv1 = 1.0f / l1;
    const int qr = qb + 16 * w + (l >> 2);
#pragma unroll
    for (int j = 0; j < 8; j++) {
        int col = h * HD + 8 * j + 2 * (l & 3);
        *(float2*)&Aout[((size_t)b * SEQ + qr) * DIMSZ + col] =
            make_float2(O[j][0] * inv0, O[j][1] * inv0);
        *(float2*)&Aout[((size_t)b * SEQ + qr + 8) * DIMSZ + col] =
            make_float2(O[j][2] * inv1, O[j][3] * inv1);
    }
}

// ---------------------------------------------------------------------------
extern "C" void kernel_launch(void* const* d_in, const int* in_sizes, int n_in,
                              void* d_out, int out_size)
{
    (void)in_sizes; (void)n_in; (void)out_size;
    const float* x    = (const float*)d_in[0];
    const float* Wq   = (const float*)d_in[1];
    const float* Wk   = (const float*)d_in[2];
    const float* Wv   = (const float*)d_in[3];
    const float* Wo   = (const float*)d_in[4];
    const int*   mask = (const int*)d_in[5];
    float*       out  = (float*)d_out;

    float *Qp = nullptr, *Kp = nullptr, *Vp = nullptr, *Ap = nullptr;
    cudaGetSymbolAddress((void**)&Qp, g_Q);
    cudaGetSymbolAddress((void**)&Kp, g_K);
    cudaGetSymbolAddress((void**)&Vp, g_V);
    cudaGetSymbolAddress((void**)&Ap, g_A);

    cudaFuncSetAttribute(gemm_tc,
                         cudaFuncAttributeMaxDynamicSharedMemorySize, G_SMEM);
    cudaFuncSetAttribute(attn_tc,
                         cudaFuncAttributeMaxDynamicSharedMemorySize, AT_SMEM);

    dim3 ggrid(DIMSZ / 64, M_TOT / 128);   // (8, 64)
    gemm_tc<<<ggrid, 256, G_SMEM>>>(x, Wq, Qp);
    gemm_tc<<<ggrid, 256, G_SMEM>>>(x, Wk, Kp);
    gemm_tc<<<ggrid, 256, G_SMEM>>>(x, Wv, Vp);

    attn_tc<<<dim3(SEQ / 128, HEADS, BSZ), 256, AT_SMEM>>>(Qp, Kp, Vp, mask, Ap);

    gemm_tc<<<ggrid, 256, G_SMEM>>>(Ap, Wo, out);
}